// round 16
// baseline (speedup 1.0000x reference)
#include <cuda_runtime.h>
#include <cuda_fp16.h>
#include <cstdint>
#include <cstddef>

// ---------------------------------------------------------------------------
// Problem constants
// ---------------------------------------------------------------------------
#define N_NODES 100
#define IN_C    65536
#define OUT_C   60
#define N_EDGES 1600
#define NSPLIT  48
#define KTILE   64
#define GTHREADS 256
#define GEMM_BLOCKS (NSPLIT * 6)     // 288
#define NBLK       (GEMM_BLOCKS + 1) // 289 <= 296 (148 SMs x occ 2): one wave
#define TAIL_BLOCKS 120

typedef unsigned int u32;

// ---------------------------------------------------------------------------
// smem word-layout (per stage, 32-bit words). Rows padded to 72 fp16.
// ---------------------------------------------------------------------------
#define AROW_W  36
#define AHI_W   0
#define ALO_W   4608
#define BHI_W   9216
#define STAGE_W 11520
#define SMEM_W  (2 * STAGE_W)
#define SMEM_B  (SMEM_W * 4)        // 92160 bytes -> 2 blocks/SM

__device__ __forceinline__ u32 smem_addr_u32(const void* p) {
    u32 a;
    asm("{ .reg .u64 t; cvta.to.shared.u64 t, %1; cvt.u32.u64 %0, t; }"
        : "=r"(a) : "l"(p));
    return a;
}
__device__ __forceinline__ void cpasync16(u32 dst, const void* src) {
    asm volatile("cp.async.cg.shared.global [%0], [%1], 16;"
                 :: "r"(dst), "l"(src) : "memory");
}
#define CPASYNC_COMMIT() asm volatile("cp.async.commit_group;" ::: "memory")
#define CPASYNC_WAIT()   asm volatile("cp.async.wait_group 0;" ::: "memory")

// mma.sync m16n8k16 row.col f32.f16.f16.f32  (fast path — f32 acc only)
__device__ __forceinline__ void mma16816(float* c, const u32* a, const u32* b) {
    asm volatile(
        "mma.sync.aligned.m16n8k16.row.col.f32.f16.f16.f32 "
        "{%0,%1,%2,%3}, {%4,%5,%6,%7}, {%8,%9}, {%0,%1,%2,%3};"
        : "+f"(c[0]), "+f"(c[1]), "+f"(c[2]), "+f"(c[3])
        : "r"(a[0]), "r"(a[1]), "r"(a[2]), "r"(a[3]), "r"(b[0]), "r"(b[1]));
}

#define LDSM4(r, addr) \
    asm volatile("ldmatrix.sync.aligned.m8n8.x4.shared.b16 {%0,%1,%2,%3}, [%4];" \
        : "=r"((r)[0]), "=r"((r)[1]), "=r"((r)[2]), "=r"((r)[3]) : "r"(addr))

// ---------------------------------------------------------------------------
// Scratch
// ---------------------------------------------------------------------------
__device__ u32   g_Xh[IN_C * N_NODES / 2];   // x hi, fp16 pairs (13.1 MB)
__device__ u32   g_Xl[IN_C * N_NODES / 2];   // x lo residual, fp16 pairs
__device__ float g_Yt[360 * 100];            // transposed Y: [col][node]
__device__ float g_A[10000];                 // normalized adjacency (Â)
__device__ float g_emb[2 * 6000];
__device__ float g_V[120];
// monotonic barrier counters (start at 0 at module load; each launch adds
// exactly N -> always a multiple of N at launch start; no reset needed)
__device__ unsigned g_s0;                    // split done  (N = NBLK)
__device__ unsigned g_s1;                    // Yt done     (N = NBLK)
__device__ unsigned g_s2;                    // emb done    (N = TAIL_BLOCKS)

__device__ __forceinline__ void gbar(unsigned* c, unsigned N, bool wait) {
    unsigned old = atomicAdd(c, 1u);
    if (wait) {
        unsigned target = old - (old % N) + N;
        while (*(volatile unsigned*)c < target) { }
    }
}

// ---------------------------------------------------------------------------
// A-tile staging via 16B cp.async (Xh/Xl fp16 in gmem/L2)
// ---------------------------------------------------------------------------
__device__ __forceinline__ void stage_A_async(u32 buf, int kb, int t) {
    #pragma unroll
    for (int i = 0; i < 4; i++) {
        int idx = t + i * GTHREADS;
        if (idx < 800) {
            int m = idx >> 3, q = idx & 7;          // q = 16B chunk
            size_t w = (size_t)m * (IN_C / 2) + (kb >> 1) + q * 4;
            u32 d = buf + (u32)((m * AROW_W + q * 4) * 4);
            cpasync16(d, g_Xh + w);
            cpasync16(d + ALO_W * 4, g_Xl + w);
        }
    }
    CPASYNC_COMMIT();
}

// ---------------------------------------------------------------------------
// THE mega-kernel: split+prep | barrier | GEMM | barrier | emb | barrier | fc
// ---------------------------------------------------------------------------
__global__ __launch_bounds__(GTHREADS, 2)
void mega_kernel(const float* __restrict__ x,
                 const int*   __restrict__ ei,
                 const float* __restrict__ vnr,
                 const float* __restrict__ aw,
                 const float* __restrict__ cw,
                 const float* __restrict__ acb,
                 const float* __restrict__ ccb,
                 const float* __restrict__ avw,
                 const float* __restrict__ avb,
                 const float* __restrict__ cvw,
                 const float* __restrict__ cvb,
                 const float* __restrict__ afw,
                 const float* __restrict__ afb,
                 const float* __restrict__ cfw,
                 const float* __restrict__ cfb,
                 float* __restrict__ out, int out_size) {
    extern __shared__ u32 smw[];
    const int b = blockIdx.x;
    const int t = threadIdx.x;

    // ================= phase 0: X split, Yt zero, prep ====================
    {
        int z = b * GTHREADS + t;
        if (z < 9000) ((float4*)g_Yt)[z] = make_float4(0.f, 0.f, 0.f, 0.f);
        for (int idx = z; idx < 1638400; idx += NBLK * GTHREADS) {
            float4 v = ((const float4*)x)[idx];
            __half h0 = __float2half_rn(v.x), h1 = __float2half_rn(v.y);
            __half h2 = __float2half_rn(v.z), h3 = __float2half_rn(v.w);
            __half l0 = __float2half_rn(v.x - __half2float(h0));
            __half l1 = __float2half_rn(v.y - __half2float(h1));
            __half l2 = __float2half_rn(v.z - __half2float(h2));
            __half l3 = __float2half_rn(v.w - __half2float(h3));
            __half2 hp01 = __halves2half2(h0, h1), hp23 = __halves2half2(h2, h3);
            __half2 lp01 = __halves2half2(l0, l1), lp23 = __halves2half2(l2, l3);
            ((uint2*)g_Xh)[idx] = make_uint2(*(u32*)&hp01, *(u32*)&hp23);
            ((uint2*)g_Xl)[idx] = make_uint2(*(u32*)&lp01, *(u32*)&lp23);
        }
    }

    if (b == GEMM_BLOCKS) {
        // ---- prep: Â, vnr sums (256 threads, smem overlay)
        float* sA   = (float*)smw;         // 10000 floats
        float* sdeg = sA + 10000;          // 100
        __syncthreads();
        for (int i = t; i < 10000; i += GTHREADS) sA[i] = 0.f;
        if (t < N_NODES) sdeg[t] = 0.f;
        __syncthreads();
        for (int e = t; e < N_EDGES; e += GTHREADS) atomicAdd(&sdeg[ei[e]], 1.f);
        __syncthreads();
        if (t < N_NODES) {
            float d = sdeg[t];
            sdeg[t] = (d > 0.f) ? rsqrtf(fmaxf(d, 1.f)) : 0.f;
        }
        __syncthreads();
        for (int e = t; e < N_EDGES; e += GTHREADS) {
            int s = ei[e];
            int d = ei[N_EDGES + e];
            atomicAdd(&sA[d * N_NODES + s], -sdeg[s] * sdeg[d]);
        }
        __syncthreads();
        for (int i = t; i < 10000; i += GTHREADS) g_A[i] = sA[i];
        if (t < OUT_C) {
            float va = 0.f, vc = 0.f;
            #pragma unroll
            for (int i = 0; i < 3; i++) {
                float v = vnr[i];
                va += v * avw[i * OUT_C + t] + avb[i * OUT_C + t];
                vc += v * cvw[i * OUT_C + t] + cvb[i * OUT_C + t];
            }
            g_V[t] = va;
            g_V[OUT_C + t] = vc;
        }
        // arrive+wait split barrier, then arrive s1 (no GEMM work) and exit
        __threadfence();
        __syncthreads();
        if (t == 0) {
            gbar(&g_s0, NBLK, true);
            gbar(&g_s1, NBLK, false);
        }
        return;
    }

    // ---- split barrier (GEMM must see full Xh/Xl)
    __threadfence();
    __syncthreads();
    if (t == 0) gbar(&g_s0, NBLK, true);
    __syncthreads();
    __threadfence();

    // ================= phase 1: GEMM (R12 config) =========================
    const int lane = t & 31, wid = t >> 5;
    const int wm = wid >> 1, wn = wid & 1;
    const bool do_mt1 = (wm < 3);
    const int hk = b / NSPLIT;
    const int ks = b - hk * NSPLIT;
    const float* Wbase = ((hk >= 3) ? cw : aw) + (size_t)(hk % 3) * IN_C * OUT_C;

    int k0 = (int)(((long long)ks * IN_C) / NSPLIT) & ~(KTILE - 1);
    int k1 = (int)(((long long)(ks + 1) * IN_C) / NSPLIT) & ~(KTILE - 1);
    const int nch = (k1 - k0) / KTILE;

    float acc[2][4][4];
    #pragma unroll
    for (int mt = 0; mt < 2; mt++)
        #pragma unroll
        for (int nt = 0; nt < 4; nt++)
            #pragma unroll
            for (int q = 0; q < 4; q++) acc[mt][nt][q] = 0.f;

    const u32 sbase = smem_addr_u32(smw);
    const int t2 = lane >> 3, rr = lane & 7;
    const u32 a_off = (u32)(((wm * 32 + rr + (t2 & 1) * 8) * AROW_W + (t2 >> 1) * 4) * 4);
    const u32 b_off = (u32)(BHI_W * 4) +
                      (u32)(((wn * 32 + rr + (t2 >> 1) * 8) * AROW_W + (t2 & 1) * 4) * 4);

    float wr[15];

    stage_A_async(sbase, k0, t);
    #pragma unroll
    for (int i = 0; i < 15; i++) {
        int idx = t + i * GTHREADS;
        int k = idx / OUT_C, ch = idx - k * OUT_C;
        wr[i] = Wbase[(size_t)(k0 + k) * OUT_C + ch];
    }
    CPASYNC_WAIT();
    __syncthreads();
    {
        u32* sb = smw;
        #pragma unroll
        for (int i = 0; i < 15; i++) {
            int idx = t + i * GTHREADS;
            int k = idx / OUT_C, ch = idx - k * OUT_C;
            ((__half*)(sb + BHI_W))[ch * 72 + k] = __float2half_rn(wr[i]);
        }
    }
    __syncthreads();

    for (int c = 0; c < nch; c++) {
        const u32 stb = sbase + ((c & 1) ? STAGE_W * 4 : 0);
        const u32 stn = sbase + ((c & 1) ? 0 : STAGE_W * 4);
        const bool more = (c + 1 < nch);

        if (more) {
            int kb = k0 + (c + 1) * KTILE;
            stage_A_async(stn, kb, t);
            #pragma unroll
            for (int i = 0; i < 15; i++) {
                int idx = t + i * GTHREADS;
                int k = idx / OUT_C, ch = idx - k * OUT_C;
                wr[i] = Wbase[(size_t)(kb + k) * OUT_C + ch];
            }
        }

        #pragma unroll
        for (int kc = 0; kc < 4; kc++) {
            const u32 ko = kc * 32;
            u32 ah0[4], ah1[4], al0[4], al1[4];
            u32 b0[4], b1[4];
            LDSM4(ah0, stb + a_off + ko);
            if (do_mt1) LDSM4(ah1, stb + a_off + 2304 + ko);
            LDSM4(al0, stb + a_off + 18432 + ko);
            if (do_mt1) LDSM4(al1, stb + a_off + 18432 + 2304 + ko);
            LDSM4(b0, stb + b_off + ko);
            LDSM4(b1, stb + b_off + 2304 + ko);

            const u32* bh[4] = { b0, b0 + 2, b1, b1 + 2 };
            #pragma unroll
            for (int nt = 0; nt < 4; nt++) {
                mma16816(acc[0][nt], ah0, bh[nt]);
                mma16816(acc[0][nt], al0, bh[nt]);
                if (do_mt1) {
                    mma16816(acc[1][nt], ah1, bh[nt]);
                    mma16816(acc[1][nt], al1, bh[nt]);
                }
            }
        }

        if (more) {
            u32* sb = smw + ((c + 1) & 1) * STAGE_W;
            #pragma unroll
            for (int i = 0; i < 15; i++) {
                int idx = t + i * GTHREADS;
                int k = idx / OUT_C, ch = idx - k * OUT_C;
                ((__half*)(sb + BHI_W))[ch * 72 + k] = __float2half_rn(wr[i]);
            }
            CPASYNC_WAIT();
        }
        __syncthreads();
    }

    // epilogue: atomicAdd into transposed Yt
    {
        const int r = lane >> 2, cb = (lane & 3) * 2;
        float* Yg = g_Yt + hk * 60 * 100;
        #pragma unroll
        for (int mt = 0; mt < 2; mt++) {
            if (mt == 1 && !do_mt1) break;
            int row = wm * 32 + mt * 16 + r;
            #pragma unroll
            for (int nt = 0; nt < 4; nt++) {
                int col = wn * 32 + nt * 8 + cb;
                if (col < OUT_C) {
                    if (row < N_NODES)     atomicAdd(Yg + col * 100 + row,     acc[mt][nt][0]);
                    if (row + 8 < N_NODES) atomicAdd(Yg + col * 100 + row + 8, acc[mt][nt][2]);
                }
                if (col + 1 < OUT_C) {
                    if (row < N_NODES)     atomicAdd(Yg + (col + 1) * 100 + row,     acc[mt][nt][1]);
                    if (row + 8 < N_NODES) atomicAdd(Yg + (col + 1) * 100 + row + 8, acc[mt][nt][3]);
                }
            }
        }
    }

    // ---- barrier s1: Yt complete
    __threadfence();
    __syncthreads();
    if (b >= TAIL_BLOCKS) {
        if (t == 0) gbar(&g_s1, NBLK, false);
        return;
    }

    // ================= phase 2: tail (blocks 0..119) ======================
    float* fs  = (float*)smw;
    float* awS = fs;              // 5000
    float* y0  = fs + 5000;
    float* y1  = fs + 5104;
    float* y2  = fs + 5208;       // 104
    float* zz  = fs + 5312;       // 104
    float* ea  = fs + 5416;       // 52
    float* ec  = fs + 5468;       // 52
    float* red = fs + 5520;       // 4
    const int h = b / OUT_C, cc = b - OUT_C * h;
    const int i0 = b * 50;

    {   // prefetch fc weight slice while spinning
        const char* src = (const char*)(afw + (size_t)i0 * 100);
        u32 sb = smem_addr_u32(awS);
        #pragma unroll
        for (int i = 0; i < 5; i++) {
            int q = t + i * GTHREADS;
            if (q < 1250) cpasync16(sb + q * 16, src + q * 16);
        }
        CPASYNC_COMMIT();
    }

    if (t == 0) gbar(&g_s1, NBLK, true);
    __syncthreads();
    __threadfence();

    // emb phases for column (h,cc)
    if (t < N_NODES) {
        y0[t] = g_Yt[(h * 180 + cc) * 100 + t];
        y1[t] = g_Yt[(h * 180 + 60 + cc) * 100 + t];
        y2[t] = g_Yt[(h * 180 + 120 + cc) * 100 + t];
    }
    __syncthreads();

    if (t < N_NODES) {
        const float4* Ar = (const float4*)(g_A + t * 100);
        float a0 = 0.f, a1 = 0.f, a2 = 0.f, a3 = 0.f;
        #pragma unroll
        for (int q = 0; q < 25; q++) {
            float4 av = Ar[q];
            a0 = fmaf(av.x, y2[q * 4 + 0], a0);
            a1 = fmaf(av.y, y2[q * 4 + 1], a1);
            a2 = fmaf(av.z, y2[q * 4 + 2], a2);
            a3 = fmaf(av.w, y2[q * 4 + 3], a3);
        }
        zz[t] = fmaf(2.f, (a0 + a1) + (a2 + a3), y1[t]);
    }
    __syncthreads();

    if (t < N_NODES) {
        const float4* Ar = (const float4*)(g_A + t * 100);
        float a0 = 0.f, a1 = 0.f, a2 = 0.f, a3 = 0.f;
        #pragma unroll
        for (int q = 0; q < 25; q++) {
            float4 av = Ar[q];
            a0 = fmaf(av.x, zz[q * 4 + 0], a0);
            a1 = fmaf(av.y, zz[q * 4 + 1], a1);
            a2 = fmaf(av.z, zz[q * 4 + 2], a2);
            a3 = fmaf(av.w, zz[q * 4 + 3], a3);
        }
        float pre = y0[t] + (a0 + a1) + (a2 + a3) - y2[t] + (h ? ccb[cc] : acb[cc]);
        g_emb[h * 6000 + t * OUT_C + cc] = tanhf(pre) + g_V[h * OUT_C + cc];
    }

    // block 0 seeds output with biases (out is poisoned pre-launch)
    if (b == 0)
        for (int j = t; j < out_size; j += GTHREADS)
            out[j] = (j < 100) ? afb[j] : ((j == 100) ? cfb[0] : 0.f);

    // ---- barrier s2: emb (and out init) complete
    __threadfence();
    __syncthreads();
    if (t == 0) gbar(&g_s2, TAIL_BLOCKS, true);
    __syncthreads();
    __threadfence();

    // fc: rows [i0, i0+50)
    if (t < 50) {
        ea[t] = g_emb[i0 + t];
        ec[t] = g_emb[6000 + i0 + t];
    }
    CPASYNC_WAIT();
    __syncthreads();

    if (t < 100) {
        float a0 = 0.f, a1 = 0.f;
        #pragma unroll 5
        for (int i = 0; i < 50; i += 2) {
            a0 = fmaf(ea[i],     awS[i * 100 + t],       a0);
            a1 = fmaf(ea[i + 1], awS[(i + 1) * 100 + t], a1);
        }
        atomicAdd(&out[t], a0 + a1);
    }

    float v = (t < 50) ? ec[t] * cfw[i0 + t] : 0.f;
    #pragma unroll
    for (int off = 16; off > 0; off >>= 1)
        v += __shfl_down_sync(0xffffffffu, v, off);
    if ((t & 31) == 0 && t < 64) red[t >> 5] = v;
    __syncthreads();
    if (t == 0 && out_size > 100)
        atomicAdd(&out[100], red[0] + red[1]);
}

// ---------------------------------------------------------------------------
// Launch
// ---------------------------------------------------------------------------
extern "C" void kernel_launch(void* const* d_in, const int* in_sizes, int n_in,
                              void* d_out, int out_size) {
    const float* x   = (const float*)d_in[0];
    const int*   ei  = (const int*)  d_in[1];
    const float* vnr = (const float*)d_in[2];
    const float* aw  = (const float*)d_in[3];
    const float* acb = (const float*)d_in[4];
    const float* cw  = (const float*)d_in[5];
    const float* ccb = (const float*)d_in[6];
    const float* avw = (const float*)d_in[7];
    const float* avb = (const float*)d_in[8];
    const float* cvw = (const float*)d_in[9];
    const float* cvb = (const float*)d_in[10];
    const float* afw = (const float*)d_in[11];
    const float* afb = (const float*)d_in[12];
    const float* cfw = (const float*)d_in[13];
    const float* cfb = (const float*)d_in[14];
    float* out = (float*)d_out;

    static int smem_set = 0;
    if (!smem_set) {
        cudaFuncSetAttribute(mega_kernel, cudaFuncAttributeMaxDynamicSharedMemorySize, SMEM_B);
        smem_set = 1;
    }

    mega_kernel<<<NBLK, GTHREADS, SMEM_B>>>(x, ei, vnr, aw, cw, acb, ccb,
                                            avw, avb, cvw, cvb,
                                            afw, afb, cfw, cfb, out, out_size);
}

// round 17
// speedup vs baseline: 1.1423x; 1.1423x over previous
#include <cuda_runtime.h>
#include <cuda_fp16.h>
#include <cstdint>
#include <cstddef>

// ---------------------------------------------------------------------------
// Problem constants
// ---------------------------------------------------------------------------
#define N_NODES 100
#define IN_C    65536
#define OUT_C   60
#define N_EDGES 1600
#define NSPLIT  48
#define KTILE   64
#define GTHREADS 256
#define GEMM_BLOCKS (NSPLIT * 6)     // 288
#define NBLK       (GEMM_BLOCKS + 1) // 289 <= 296: still one occ-2 wave
#define TAIL_BLOCKS 120

typedef unsigned int u32;

// ---------------------------------------------------------------------------
// smem word-layout (per stage, 32-bit words). Rows padded to 72 fp16.
// ---------------------------------------------------------------------------
#define AROW_W  36
#define AHI_W   0
#define ALO_W   4608
#define BHI_W   9216
#define STAGE_W 11520
#define SMEM_W  (2 * STAGE_W)
#define SMEM_B  (SMEM_W * 4)        // 92160 bytes -> 2 blocks/SM

__device__ __forceinline__ u32 smem_addr_u32(const void* p) {
    u32 a;
    asm("{ .reg .u64 t; cvta.to.shared.u64 t, %1; cvt.u32.u64 %0, t; }"
        : "=r"(a) : "l"(p));
    return a;
}
__device__ __forceinline__ void cpasync16(u32 dst, const void* src) {
    asm volatile("cp.async.cg.shared.global [%0], [%1], 16;"
                 :: "r"(dst), "l"(src) : "memory");
}
#define CPASYNC_COMMIT() asm volatile("cp.async.commit_group;" ::: "memory")
#define CPASYNC_WAIT()   asm volatile("cp.async.wait_group 0;" ::: "memory")

// mma.sync m16n8k16 row.col f32.f16.f16.f32  (fast path — f32 acc only)
__device__ __forceinline__ void mma16816(float* c, const u32* a, const u32* b) {
    asm volatile(
        "mma.sync.aligned.m16n8k16.row.col.f32.f16.f16.f32 "
        "{%0,%1,%2,%3}, {%4,%5,%6,%7}, {%8,%9}, {%0,%1,%2,%3};"
        : "+f"(c[0]), "+f"(c[1]), "+f"(c[2]), "+f"(c[3])
        : "r"(a[0]), "r"(a[1]), "r"(a[2]), "r"(a[3]), "r"(b[0]), "r"(b[1]));
}

#define LDSM4(r, addr) \
    asm volatile("ldmatrix.sync.aligned.m8n8.x4.shared.b16 {%0,%1,%2,%3}, [%4];" \
        : "=r"((r)[0]), "=r"((r)[1]), "=r"((r)[2]), "=r"((r)[3]) : "r"(addr))

// ---------------------------------------------------------------------------
// Scratch
// ---------------------------------------------------------------------------
__device__ u32   g_Xh[IN_C * N_NODES / 2];   // x hi, fp16 pairs (13.1 MB)
__device__ u32   g_Xl[IN_C * N_NODES / 2];   // x lo residual, fp16 pairs
__device__ float g_Yt[360 * 100];            // transposed Y: [col][node]
__device__ float g_A[10000];                 // normalized adjacency (Â)
__device__ float g_emb[2 * 6000];
__device__ float g_V[120];
// monotonic barrier counters: zero at module load; each launch adds exactly
// N -> multiple of N at every launch start; no reset needed (replay-safe)
__device__ unsigned g_s1;                    // prep+Yt done (N = NBLK)
__device__ unsigned g_s2;                    // emb done     (N = TAIL_BLOCKS)

__device__ __forceinline__ void gbar(unsigned* c, unsigned N, bool wait) {
    unsigned old = atomicAdd(c, 1u);
    if (wait) {
        unsigned target = old - (old % N) + N;
        while (*(volatile unsigned*)c < target) { }
    }
}

// ---------------------------------------------------------------------------
// Kernel 0: split X into fp16 hi/lo; first 36 blocks also zero Yt
// ---------------------------------------------------------------------------
__global__ void xsplit_kernel(const float* __restrict__ x) {
    int idx = blockIdx.x * 256 + threadIdx.x;       // 1,638,400 float4
    if (blockIdx.x < 36) {
        int z = blockIdx.x * 256 + threadIdx.x;
        if (z < 9000) ((float4*)g_Yt)[z] = make_float4(0.f, 0.f, 0.f, 0.f);
    }
    float4 v = ((const float4*)x)[idx];
    __half h0 = __float2half_rn(v.x), h1 = __float2half_rn(v.y);
    __half h2 = __float2half_rn(v.z), h3 = __float2half_rn(v.w);
    __half l0 = __float2half_rn(v.x - __half2float(h0));
    __half l1 = __float2half_rn(v.y - __half2float(h1));
    __half l2 = __float2half_rn(v.z - __half2float(h2));
    __half l3 = __float2half_rn(v.w - __half2float(h3));
    __half2 hp01 = __halves2half2(h0, h1), hp23 = __halves2half2(h2, h3);
    __half2 lp01 = __halves2half2(l0, l1), lp23 = __halves2half2(l2, l3);
    ((uint2*)g_Xh)[idx] = make_uint2(*(u32*)&hp01, *(u32*)&hp23);
    ((uint2*)g_Xl)[idx] = make_uint2(*(u32*)&lp01, *(u32*)&lp23);
}

// ---------------------------------------------------------------------------
// A-tile staging via 16B cp.async (Xh/Xl fp16 in gmem/L2)
// ---------------------------------------------------------------------------
__device__ __forceinline__ void stage_A_async(u32 buf, int kb, int t) {
    #pragma unroll
    for (int i = 0; i < 4; i++) {
        int idx = t + i * GTHREADS;
        if (idx < 800) {
            int m = idx >> 3, q = idx & 7;          // q = 16B chunk
            size_t w = (size_t)m * (IN_C / 2) + (kb >> 1) + q * 4;
            u32 d = buf + (u32)((m * AROW_W + q * 4) * 4);
            cpasync16(d, g_Xh + w);
            cpasync16(d + ALO_W * 4, g_Xl + w);
        }
    }
    CPASYNC_COMMIT();
}

// ---------------------------------------------------------------------------
// Kernel 1: GEMM (+289th prep block) + grid-sync + tail (emb + fc)
// ---------------------------------------------------------------------------
__global__ __launch_bounds__(GTHREADS, 2)
void gemm_mma(const float* __restrict__ aw,
              const float* __restrict__ cw,
              const int*   __restrict__ ei,
              const float* __restrict__ vnr,
              const float* __restrict__ avw,
              const float* __restrict__ avb,
              const float* __restrict__ cvw,
              const float* __restrict__ cvb,
              const float* __restrict__ afb,
              const float* __restrict__ cfb,
              const float* __restrict__ acb,
              const float* __restrict__ ccb,
              const float* __restrict__ afw,
              const float* __restrict__ cfw,
              float* __restrict__ out, int out_size) {
    extern __shared__ u32 smw[];
    const int b = blockIdx.x;
    const int t = threadIdx.x;

    // ================= prep block (runs concurrently with GEMM) ==========
    if (b == GEMM_BLOCKS) {
        float* sA   = (float*)smw;         // 10000 floats
        float* sdeg = sA + 10000;          // 100
        for (int i = t; i < 10000; i += GTHREADS) sA[i] = 0.f;
        if (t < N_NODES) sdeg[t] = 0.f;
        __syncthreads();
        for (int e = t; e < N_EDGES; e += GTHREADS) atomicAdd(&sdeg[ei[e]], 1.f);
        __syncthreads();
        if (t < N_NODES) {
            float d = sdeg[t];
            sdeg[t] = (d > 0.f) ? rsqrtf(fmaxf(d, 1.f)) : 0.f;
        }
        __syncthreads();
        for (int e = t; e < N_EDGES; e += GTHREADS) {
            int s = ei[e];
            int d = ei[N_EDGES + e];
            atomicAdd(&sA[d * N_NODES + s], -sdeg[s] * sdeg[d]);
        }
        __syncthreads();
        for (int i = t; i < 10000; i += GTHREADS) g_A[i] = sA[i];
        if (t < OUT_C) {
            float va = 0.f, vc = 0.f;
            #pragma unroll
            for (int i = 0; i < 3; i++) {
                float v = vnr[i];
                va += v * avw[i * OUT_C + t] + avb[i * OUT_C + t];
                vc += v * cvw[i * OUT_C + t] + cvb[i * OUT_C + t];
            }
            g_V[t] = va;
            g_V[OUT_C + t] = vc;
        }
        for (int j = t; j < out_size; j += GTHREADS)
            out[j] = (j < 100) ? afb[j] : ((j == 100) ? cfb[0] : 0.f);
        __threadfence();
        __syncthreads();
        if (t == 0) gbar(&g_s1, NBLK, false);
        return;
    }

    // ================= GEMM blocks (exact R12/R15 config) =================
    const int lane = t & 31, wid = t >> 5;
    const int wm = wid >> 1, wn = wid & 1;
    const bool do_mt1 = (wm < 3);          // rows 112-127: all pad
    const int hk = b / NSPLIT;
    const int ks = b - hk * NSPLIT;
    const float* Wbase = ((hk >= 3) ? cw : aw) + (size_t)(hk % 3) * IN_C * OUT_C;

    int k0 = (int)(((long long)ks * IN_C) / NSPLIT) & ~(KTILE - 1);
    int k1 = (int)(((long long)(ks + 1) * IN_C) / NSPLIT) & ~(KTILE - 1);
    const int nch = (k1 - k0) / KTILE;

    float acc[2][4][4];
    #pragma unroll
    for (int mt = 0; mt < 2; mt++)
        #pragma unroll
        for (int nt = 0; nt < 4; nt++)
            #pragma unroll
            for (int q = 0; q < 4; q++) acc[mt][nt][q] = 0.f;

    const u32 sbase = smem_addr_u32(smw);
    const int t2 = lane >> 3, rr = lane & 7;
    const u32 a_off = (u32)(((wm * 32 + rr + (t2 & 1) * 8) * AROW_W + (t2 >> 1) * 4) * 4);
    const u32 b_off = (u32)(BHI_W * 4) +
                      (u32)(((wn * 32 + rr + (t2 >> 1) * 8) * AROW_W + (t2 & 1) * 4) * 4);

    float wr[15];

    stage_A_async(sbase, k0, t);
    #pragma unroll
    for (int i = 0; i < 15; i++) {
        int idx = t + i * GTHREADS;
        int k = idx / OUT_C, ch = idx - k * OUT_C;
        wr[i] = Wbase[(size_t)(k0 + k) * OUT_C + ch];
    }
    CPASYNC_WAIT();
    __syncthreads();
    {
        u32* sb = smw;
        #pragma unroll
        for (int i = 0; i < 15; i++) {
            int idx = t + i * GTHREADS;
            int k = idx / OUT_C, ch = idx - k * OUT_C;
            ((__half*)(sb + BHI_W))[ch * 72 + k] = __float2half_rn(wr[i]);
        }
    }
    __syncthreads();

    for (int c = 0; c < nch; c++) {
        const u32 stb = sbase + ((c & 1) ? STAGE_W * 4 : 0);
        const u32 stn = sbase + ((c & 1) ? 0 : STAGE_W * 4);
        const bool more = (c + 1 < nch);

        if (more) {
            int kb = k0 + (c + 1) * KTILE;
            stage_A_async(stn, kb, t);
            #pragma unroll
            for (int i = 0; i < 15; i++) {
                int idx = t + i * GTHREADS;
                int k = idx / OUT_C, ch = idx - k * OUT_C;
                wr[i] = Wbase[(size_t)(kb + k) * OUT_C + ch];
            }
        }

        #pragma unroll
        for (int kc = 0; kc < 4; kc++) {
            const u32 ko = kc * 32;
            u32 ah0[4], ah1[4], al0[4], al1[4];
            u32 b0[4], b1[4];
            LDSM4(ah0, stb + a_off + ko);
            if (do_mt1) LDSM4(ah1, stb + a_off + 2304 + ko);
            LDSM4(al0, stb + a_off + 18432 + ko);
            if (do_mt1) LDSM4(al1, stb + a_off + 18432 + 2304 + ko);
            LDSM4(b0, stb + b_off + ko);
            LDSM4(b1, stb + b_off + 2304 + ko);

            const u32* bh[4] = { b0, b0 + 2, b1, b1 + 2 };
            #pragma unroll
            for (int nt = 0; nt < 4; nt++) {
                mma16816(acc[0][nt], ah0, bh[nt]);
                mma16816(acc[0][nt], al0, bh[nt]);
                if (do_mt1) {
                    mma16816(acc[1][nt], ah1, bh[nt]);
                    mma16816(acc[1][nt], al1, bh[nt]);
                }
            }
        }

        if (more) {
            u32* sb = smw + ((c + 1) & 1) * STAGE_W;
            #pragma unroll
            for (int i = 0; i < 15; i++) {
                int idx = t + i * GTHREADS;
                int k = idx / OUT_C, ch = idx - k * OUT_C;
                ((__half*)(sb + BHI_W))[ch * 72 + k] = __float2half_rn(wr[i]);
            }
            CPASYNC_WAIT();
        }
        __syncthreads();
    }

    // epilogue: atomicAdd into transposed Yt
    {
        const int r = lane >> 2, cb = (lane & 3) * 2;
        float* Yg = g_Yt + hk * 60 * 100;
        #pragma unroll
        for (int mt = 0; mt < 2; mt++) {
            if (mt == 1 && !do_mt1) break;
            int row = wm * 32 + mt * 16 + r;
            #pragma unroll
            for (int nt = 0; nt < 4; nt++) {
                int col = wn * 32 + nt * 8 + cb;
                if (col < OUT_C) {
                    if (row < N_NODES)     atomicAdd(Yg + col * 100 + row,     acc[mt][nt][0]);
                    if (row + 8 < N_NODES) atomicAdd(Yg + col * 100 + row + 8, acc[mt][nt][2]);
                }
                if (col + 1 < OUT_C) {
                    if (row < N_NODES)     atomicAdd(Yg + (col + 1) * 100 + row,     acc[mt][nt][1]);
                    if (row + 8 < N_NODES) atomicAdd(Yg + (col + 1) * 100 + row + 8, acc[mt][nt][3]);
                }
            }
        }
    }

    // ---- barrier s1: Yt + prep complete
    __threadfence();
    __syncthreads();
    if (b >= TAIL_BLOCKS) {
        if (t == 0) gbar(&g_s1, NBLK, false);
        return;
    }

    // ================= tail (blocks 0..119) ===============================
    float* fs  = (float*)smw;
    float* awS = fs;              // 5000
    float* y0  = fs + 5000;
    float* y1  = fs + 5104;
    float* y2  = fs + 5208;       // 104
    float* zz  = fs + 5312;       // 104
    float* ea  = fs + 5416;       // 52
    float* ec  = fs + 5468;       // 52
    float* red = fs + 5520;       // 4
    const int h = b / OUT_C, cc = b - OUT_C * h;
    const int i0 = b * 50;

    {   // prefetch fc weight slice while waiting
        const char* src = (const char*)(afw + (size_t)i0 * 100);
        u32 sb = smem_addr_u32(awS);
        #pragma unroll
        for (int i = 0; i < 5; i++) {
            int q = t + i * GTHREADS;
            if (q < 1250) cpasync16(sb + q * 16, src + q * 16);
        }
        CPASYNC_COMMIT();
    }

    if (t == 0) gbar(&g_s1, NBLK, true);
    __syncthreads();
    __threadfence();

    // emb phases for column (h,cc)
    if (t < N_NODES) {
        y0[t] = g_Yt[(h * 180 + cc) * 100 + t];
        y1[t] = g_Yt[(h * 180 + 60 + cc) * 100 + t];
        y2[t] = g_Yt[(h * 180 + 120 + cc) * 100 + t];
    }
    __syncthreads();

    if (t < N_NODES) {
        const float4* Ar = (const float4*)(g_A + t * 100);
        float a0 = 0.f, a1 = 0.f, a2 = 0.f, a3 = 0.f;
        #pragma unroll
        for (int q = 0; q < 25; q++) {
            float4 av = Ar[q];
            a0 = fmaf(av.x, y2[q * 4 + 0], a0);
            a1 = fmaf(av.y, y2[q * 4 + 1], a1);
            a2 = fmaf(av.z, y2[q * 4 + 2], a2);
            a3 = fmaf(av.w, y2[q * 4 + 3], a3);
        }
        zz[t] = fmaf(2.f, (a0 + a1) + (a2 + a3), y1[t]);
    }
    __syncthreads();

    if (t < N_NODES) {
        const float4* Ar = (const float4*)(g_A + t * 100);
        float a0 = 0.f, a1 = 0.f, a2 = 0.f, a3 = 0.f;
        #pragma unroll
        for (int q = 0; q < 25; q++) {
            float4 av = Ar[q];
            a0 = fmaf(av.x, zz[q * 4 + 0], a0);
            a1 = fmaf(av.y, zz[q * 4 + 1], a1);
            a2 = fmaf(av.z, zz[q * 4 + 2], a2);
            a3 = fmaf(av.w, zz[q * 4 + 3], a3);
        }
        float pre = y0[t] + (a0 + a1) + (a2 + a3) - y2[t] + (h ? ccb[cc] : acb[cc]);
        g_emb[h * 6000 + t * OUT_C + cc] = tanhf(pre) + g_V[h * OUT_C + cc];
    }

    // ---- barrier s2: emb complete
    __threadfence();
    __syncthreads();
    if (t == 0) gbar(&g_s2, TAIL_BLOCKS, true);
    __syncthreads();
    __threadfence();

    // fc: rows [i0, i0+50)
    if (t < 50) {
        ea[t] = g_emb[i0 + t];
        ec[t] = g_emb[6000 + i0 + t];
    }
    CPASYNC_WAIT();
    __syncthreads();

    if (t < 100) {
        float a0 = 0.f, a1 = 0.f;
        #pragma unroll 5
        for (int i = 0; i < 50; i += 2) {
            a0 = fmaf(ea[i],     awS[i * 100 + t],       a0);
            a1 = fmaf(ea[i + 1], awS[(i + 1) * 100 + t], a1);
        }
        atomicAdd(&out[t], a0 + a1);
    }

    float v = (t < 50) ? ec[t] * cfw[i0 + t] : 0.f;
    #pragma unroll
    for (int off = 16; off > 0; off >>= 1)
        v += __shfl_down_sync(0xffffffffu, v, off);
    if ((t & 31) == 0 && t < 64) red[t >> 5] = v;
    __syncthreads();
    if (t == 0 && out_size > 100)
        atomicAdd(&out[100], red[0] + red[1]);
}

// ---------------------------------------------------------------------------
// Launch
// ---------------------------------------------------------------------------
extern "C" void kernel_launch(void* const* d_in, const int* in_sizes, int n_in,
                              void* d_out, int out_size) {
    const float* x   = (const float*)d_in[0];
    const int*   ei  = (const int*)  d_in[1];
    const float* vnr = (const float*)d_in[2];
    const float* aw  = (const float*)d_in[3];
    const float* acb = (const float*)d_in[4];
    const float* cw  = (const float*)d_in[5];
    const float* ccb = (const float*)d_in[6];
    const float* avw = (const float*)d_in[7];
    const float* avb = (const float*)d_in[8];
    const float* cvw = (const float*)d_in[9];
    const float* cvb = (const float*)d_in[10];
    const float* afw = (const float*)d_in[11];
    const float* afb = (const float*)d_in[12];
    const float* cfw = (const float*)d_in[13];
    const float* cfb = (const float*)d_in[14];
    float* out = (float*)d_out;

    static int smem_set = 0;
    if (!smem_set) {
        cudaFuncSetAttribute(gemm_mma, cudaFuncAttributeMaxDynamicSharedMemorySize, SMEM_B);
        smem_set = 1;
    }

    xsplit_kernel<<<6400, 256>>>(x);
    gemm_mma<<<NBLK, GTHREADS, SMEM_B>>>(aw, cw, ei, vnr, avw, avb, cvw, cvb,
                                         afb, cfb, acb, ccb, afw, cfw,
                                         out, out_size);
}